// round 2
// baseline (speedup 1.0000x reference)
#include <cuda_runtime.h>
#include <cuda_bf16.h>
#include <math.h>

// Problem constants
#define N_TOK   32768      // 32 * 32 * 32
#define N_E     1024
#define E_DIM   64
#define N_ELEM  2097152    // 32*64*32*32
#define HW      1024
#define BETA    0.25f
#define DECAY   0.99f
#define EPSF    1e-5f

// Output layout (flattened reference tuple, float32)
#define O_LOSS   0
#define O_ZQ     1
#define O_PERP   (1 + N_ELEM)                       // 2097153
#define O_MINENC (2 + N_ELEM)                       // 2097154
#define O_IDX    (2 + N_ELEM + (size_t)N_TOK*N_E)   // 35651586
#define OUT_TOTAL (O_IDX + N_TOK)

// Scratch (no allocations allowed -> device globals)
__device__ int   g_idx[N_TOK];
__device__ float g_enorm[N_E];
__device__ float g_cs[N_E];
__device__ float g_sum[N_E * E_DIM];
__device__ float g_emb[N_E * E_DIM];
__device__ float g_loss_acc;

// ---------------------------------------------------------------------------
// Kernel 0: codebook norms + zero scratch
// ---------------------------------------------------------------------------
__global__ void k_prep(const float* __restrict__ emb) {
    int j = blockIdx.x * 256 + threadIdx.x;
    if (j < N_E) {
        const float* e = emb + j * E_DIM;
        float s0 = 0.f, s1 = 0.f, s2 = 0.f, s3 = 0.f;
        #pragma unroll
        for (int c = 0; c < E_DIM; c += 4) {
            s0 = __fmaf_rn(e[c+0], e[c+0], s0);
            s1 = __fmaf_rn(e[c+1], e[c+1], s1);
            s2 = __fmaf_rn(e[c+2], e[c+2], s2);
            s3 = __fmaf_rn(e[c+3], e[c+3], s3);
        }
        g_enorm[j] = __fadd_rn(__fadd_rn(s0, s1), __fadd_rn(s2, s3));
        g_cs[j] = 0.f;
        #pragma unroll
        for (int c = 0; c < E_DIM; ++c) g_sum[j * E_DIM + c] = 0.f;
        if (j == 0) g_loss_acc = 0.f;
    }
}

// ---------------------------------------------------------------------------
// Kernel 1: per-token argmin over 1024 codes (fp32 GEMM + running min),
// plus writes idx (int + float) and the one-hot "1" entries.
//
// 256 blocks x 128 threads, 1 token per thread, z row held in registers.
// Code tiles of 64 are broadcast from shared memory (LDS.128, conflict-free).
// Distance mimics reference rounding: d = (||z||^2 + ||e||^2) - 2*dot,
// intrinsics prevent FMA contraction of the final ops.
// ---------------------------------------------------------------------------
#define ST 68   // padded row stride (floats), 16B aligned

__global__ __launch_bounds__(128, 2)
void k_argmin(const float* __restrict__ z,
              const float* __restrict__ emb,
              float* __restrict__ out) {
    __shared__ float tile[64 * ST];
    __shared__ float sn[64];

    const int t   = threadIdx.x;          // 0..127
    const int n0  = blockIdx.x * 128;     // first token of block (same batch b)
    const int b   = n0 >> 10;
    const int hw0 = n0 & 1023;
    const float* zb = z + (size_t)b * E_DIM * HW;

    // ---- stage z for this block's 128 tokens (2 groups of 64), copy own row to regs
    float4 zr[16];
    const int myGroup = t >> 6;
    #pragma unroll
    for (int g = 0; g < 2; ++g) {
        __syncthreads();
        #pragma unroll
        for (int k = 0; k < 32; ++k) {
            int c = k * 2 + (t >> 6);
            int i = t & 63;
            tile[i * ST + c] = zb[c * HW + hw0 + g * 64 + i];
        }
        __syncthreads();
        if (myGroup == g) {
            int local = t & 63;
            #pragma unroll
            for (int q = 0; q < 16; ++q)
                zr[q] = *reinterpret_cast<const float4*>(&tile[local * ST + 4 * q]);
        }
    }

    // ||z||^2 (common-mode per token; ordering-safe)
    float a0 = 0.f, a1 = 0.f, a2 = 0.f, a3 = 0.f;
    #pragma unroll
    for (int q = 0; q < 16; ++q) {
        a0 = __fmaf_rn(zr[q].x, zr[q].x, a0);
        a1 = __fmaf_rn(zr[q].y, zr[q].y, a1);
        a2 = __fmaf_rn(zr[q].z, zr[q].z, a2);
        a3 = __fmaf_rn(zr[q].w, zr[q].w, a3);
    }
    const float zn = __fadd_rn(__fadd_rn(a0, a1), __fadd_rn(a2, a3));

    float best = 3.4e38f;
    int bestIdx = 0;

    for (int tile0 = 0; tile0 < N_E; tile0 += 64) {
        __syncthreads();
        #pragma unroll
        for (int k = 0; k < 32; ++k) {
            int j = k * 2 + (t >> 6);
            int c = t & 63;
            tile[j * ST + c] = emb[(tile0 + j) * E_DIM + c];
        }
        if (t < 64) sn[t] = g_enorm[tile0 + t];
        __syncthreads();

        #pragma unroll 8
        for (int j = 0; j < 64; ++j) {
            const float4* e4 = reinterpret_cast<const float4*>(&tile[j * ST]);
            float d0 = 0.f, d1 = 0.f, d2 = 0.f, d3 = 0.f;
            #pragma unroll
            for (int q = 0; q < 16; ++q) {
                float4 e = e4[q];
                d0 = __fmaf_rn(zr[q].x, e.x, d0);
                d1 = __fmaf_rn(zr[q].y, e.y, d1);
                d2 = __fmaf_rn(zr[q].z, e.z, d2);
                d3 = __fmaf_rn(zr[q].w, e.w, d3);
            }
            float dot = __fadd_rn(__fadd_rn(d0, d1), __fadd_rn(d2, d3));
            // d = (zn + en_j) - 2*dot, with the reference's double rounding
            float dval = __fadd_rn(__fadd_rn(zn, sn[j]), -__fmul_rn(2.0f, dot));
            if (dval < best) { best = dval; bestIdx = tile0 + j; }
        }
    }

    const int n = n0 + t;
    g_idx[n] = bestIdx;
    out[O_IDX + n] = (float)bestIdx;
    out[O_MINENC + (size_t)n * N_E + bestIdx] = 1.0f;
}

// ---------------------------------------------------------------------------
// Kernel 2: scatter-add cluster stats
// ---------------------------------------------------------------------------
__global__ void k_scatter(const float* __restrict__ z) {
    int i = blockIdx.x * 256 + threadIdx.x;
    if (i < N_ELEM) {
        int hw = i & 1023;
        int c  = (i >> 10) & 63;
        int b  = i >> 16;
        int n  = (b << 10) | hw;
        int idx = g_idx[n];
        atomicAdd(&g_sum[idx * E_DIM + c], z[i]);
        if (c == 0) atomicAdd(&g_cs[idx], 1.0f);
    }
}

// ---------------------------------------------------------------------------
// Kernel 3: EMA update, new codebook, perplexity (one block, 1024 threads)
// ---------------------------------------------------------------------------
__global__ void k_update(const float* __restrict__ ema_cs,
                         const float* __restrict__ ema_w,
                         float* __restrict__ out) {
    __shared__ float red[1024];
    const int j = threadIdx.x;
    const float KD = (float)(1.0 - 0.99);   // matches reference 1-decay

    float cs  = g_cs[j];
    float ncs = __fadd_rn(__fmul_rn(DECAY, ema_cs[j]), __fmul_rn(KD, cs));

    // n = sum(new_cs)
    red[j] = ncs;
    __syncthreads();
    for (int s = 512; s > 0; s >>= 1) {
        if (j < s) red[j] = __fadd_rn(red[j], red[j + s]);
        __syncthreads();
    }
    float nsum = red[0];
    __syncthreads();

    float csn = __fmul_rn(__fdiv_rn(__fadd_rn(ncs, EPSF),
                                    __fadd_rn(nsum, (float)N_E * EPSF)), nsum);

    #pragma unroll 4
    for (int c = 0; c < E_DIM; ++c) {
        float nw = __fadd_rn(__fmul_rn(DECAY, ema_w[j * E_DIM + c]),
                             __fmul_rn(KD, g_sum[j * E_DIM + c]));
        g_emb[j * E_DIM + c] = __fdiv_rn(nw, csn);
    }

    // perplexity from raw cluster_size
    float avg = cs * (1.0f / (float)N_TOK);
    float pt  = __fmul_rn(avg, logf(__fadd_rn(avg, 1e-10f)));
    red[j] = pt;
    __syncthreads();
    for (int s = 512; s > 0; s >>= 1) {
        if (j < s) red[j] = __fadd_rn(red[j], red[j + s]);
        __syncthreads();
    }
    if (j == 0) out[O_PERP] = expf(-red[0]);
}

// ---------------------------------------------------------------------------
// Kernel 4: z_q gather, straight-through output, loss accumulation
// ---------------------------------------------------------------------------
__global__ void k_zq(const float* __restrict__ z, float* __restrict__ out) {
    __shared__ float warpsum[8];
    int i = blockIdx.x * 256 + threadIdx.x;
    float acc = 0.f;
    if (i < N_ELEM) {
        int hw = i & 1023;
        int c  = (i >> 10) & 63;
        int b  = i >> 16;
        int n  = (b << 10) | hw;
        float q  = g_emb[g_idx[n] * E_DIM + c];
        float zv = z[i];
        float dq = __fsub_rn(q, zv);             // stop_grad(z_q) - z
        out[O_ZQ + i] = __fadd_rn(zv, dq);       // z + (z_q - z), ref rounding
        acc = __fmul_rn(dq, dq);
    }
    // block reduce
    #pragma unroll
    for (int s = 16; s > 0; s >>= 1)
        acc += __shfl_down_sync(0xffffffffu, acc, s);
    int lane = threadIdx.x & 31, wid = threadIdx.x >> 5;
    if (lane == 0) warpsum[wid] = acc;
    __syncthreads();
    if (wid == 0) {
        float v = (lane < 8) ? warpsum[lane] : 0.f;
        #pragma unroll
        for (int s = 4; s > 0; s >>= 1)
            v += __shfl_down_sync(0xffffffffu, v, s);
        if (lane == 0) atomicAdd(&g_loss_acc, v);
    }
}

// ---------------------------------------------------------------------------
// Kernel 5: finalize loss
// ---------------------------------------------------------------------------
__global__ void k_loss(float* __restrict__ out) {
    out[O_LOSS] = __fmul_rn(BETA, __fdiv_rn(g_loss_acc, (float)N_ELEM));
}

// ---------------------------------------------------------------------------
extern "C" void kernel_launch(void* const* d_in, const int* in_sizes, int n_in,
                              void* d_out, int out_size) {
    const float* z      = (const float*)d_in[0];
    const float* emb_w  = (const float*)d_in[1];
    const float* ema_cs = (const float*)d_in[2];
    const float* ema_w  = (const float*)d_in[3];
    float* out = (float*)d_out;

    // zero the one-hot region (everything else is fully written)
    cudaMemsetAsync(out + O_MINENC, 0, (size_t)N_TOK * N_E * sizeof(float), 0);

    k_prep<<<(N_E + 255) / 256, 256>>>(emb_w);
    k_argmin<<<N_TOK / 128, 128>>>(z, emb_w, out);
    k_scatter<<<(N_ELEM + 255) / 256, 256>>>(z);
    k_update<<<1, 1024>>>(ema_cs, ema_w, out);
    k_zq<<<(N_ELEM + 255) / 256, 256>>>(z, out);
    k_loss<<<1, 1>>>(out);
}

// round 3
// speedup vs baseline: 1.2756x; 1.2756x over previous
#include <cuda_runtime.h>
#include <cuda_bf16.h>
#include <math.h>

// Problem constants
#define N_TOK   32768      // 32 * 32 * 32
#define N_E     1024
#define E_DIM   64
#define N_ELEM  2097152    // 32*64*32*32
#define HW      1024
#define BETA    0.25f
#define DECAY   0.99f
#define EPSF    1e-5f

// Output layout (flattened reference tuple, float32)
#define O_LOSS   0
#define O_ZQ     1
#define O_PERP   (1 + N_ELEM)                       // 2097153
#define O_MINENC (2 + N_ELEM)                       // 2097154
#define O_IDX    (2 + N_ELEM + (size_t)N_TOK*N_E)   // 35651586

// Scratch (no allocations allowed -> device globals)
__device__ int   g_idx[N_TOK];
__device__ float g_enorm[N_E];
__device__ float g_cs[N_E];
__device__ float g_csn[N_E];
__device__ float g_sum[N_E * E_DIM];
__device__ float g_emb[N_E * E_DIM];
__device__ float g_loss_acc;

// ---------------------------------------------------------------------------
// Kernel 0: codebook norms + zero scratch
// ---------------------------------------------------------------------------
__global__ void k_prep(const float* __restrict__ emb) {
    int j = blockIdx.x * 256 + threadIdx.x;
    if (j < N_E) {
        const float* e = emb + j * E_DIM;
        float s0 = 0.f, s1 = 0.f, s2 = 0.f, s3 = 0.f;
        #pragma unroll
        for (int c = 0; c < E_DIM; c += 4) {
            s0 = __fmaf_rn(e[c+0], e[c+0], s0);
            s1 = __fmaf_rn(e[c+1], e[c+1], s1);
            s2 = __fmaf_rn(e[c+2], e[c+2], s2);
            s3 = __fmaf_rn(e[c+3], e[c+3], s3);
        }
        g_enorm[j] = __fadd_rn(__fadd_rn(s0, s1), __fadd_rn(s2, s3));
        g_cs[j] = 0.f;
        #pragma unroll
        for (int c = 0; c < E_DIM; ++c) g_sum[j * E_DIM + c] = 0.f;
        if (j == 0) g_loss_acc = 0.f;
    }
}

// ---------------------------------------------------------------------------
// Kernel 1: per-token argmin over 1024 codes (fp32 GEMM + running min).
// Also (fused, hidden under the FFMA stream):
//   - writes idx (int + float)
//   - zeroes + sets this token's one-hot row (float2 stores; row base 8B-aligned)
//   - scatter-adds cluster stats straight from the register-resident z row
// ---------------------------------------------------------------------------
#define ST 68   // padded row stride (floats), 16B aligned

__global__ __launch_bounds__(128, 2)
void k_argmin(const float* __restrict__ z,
              const float* __restrict__ emb,
              float* __restrict__ out) {
    __shared__ float tile[64 * ST];
    __shared__ float sn[64];

    const int t   = threadIdx.x;          // 0..127
    const int n0  = blockIdx.x * 128;     // first token of block (same batch b)
    const int b   = n0 >> 10;
    const int hw0 = n0 & 1023;
    const float* zb = z + (size_t)b * E_DIM * HW;

    // ---- stage z for this block's 128 tokens (2 groups of 64), copy own row to regs
    float4 zr[16];
    const int myGroup = t >> 6;
    #pragma unroll
    for (int g = 0; g < 2; ++g) {
        __syncthreads();
        #pragma unroll
        for (int k = 0; k < 32; ++k) {
            int c = k * 2 + (t >> 6);
            int i = t & 63;
            tile[i * ST + c] = zb[c * HW + hw0 + g * 64 + i];
        }
        __syncthreads();
        if (myGroup == g) {
            int local = t & 63;
            #pragma unroll
            for (int q = 0; q < 16; ++q)
                zr[q] = *reinterpret_cast<const float4*>(&tile[local * ST + 4 * q]);
        }
    }

    // ||z||^2 (common-mode per token; ordering-safe)
    float a0 = 0.f, a1 = 0.f, a2 = 0.f, a3 = 0.f;
    #pragma unroll
    for (int q = 0; q < 16; ++q) {
        a0 = __fmaf_rn(zr[q].x, zr[q].x, a0);
        a1 = __fmaf_rn(zr[q].y, zr[q].y, a1);
        a2 = __fmaf_rn(zr[q].z, zr[q].z, a2);
        a3 = __fmaf_rn(zr[q].w, zr[q].w, a3);
    }
    const float zn = __fadd_rn(__fadd_rn(a0, a1), __fadd_rn(a2, a3));

    float best = 3.4e38f;
    int bestIdx = 0;

    const int n = n0 + t;
    float* row = out + O_MINENC + (size_t)n * N_E;  // one-hot row (8B-aligned)
    const float2 zero2 = make_float2(0.f, 0.f);

    for (int tile0 = 0; tile0 < N_E; tile0 += 64) {
        __syncthreads();
        #pragma unroll
        for (int k = 0; k < 32; ++k) {
            int j = k * 2 + (t >> 6);
            int c = t & 63;
            tile[j * ST + c] = emb[(tile0 + j) * E_DIM + c];
        }
        if (t < 64) sn[t] = g_enorm[tile0 + t];
        __syncthreads();

        // interleave 32 float2 zero-stores of this token's one-hot slice with
        // the compute for this 64-code tile (DRAM writes hide under FFMA)
        {
            float2* seg = reinterpret_cast<float2*>(row + tile0);
            #pragma unroll 8
            for (int q = 0; q < 32; ++q) seg[q] = zero2;
        }

        #pragma unroll 8
        for (int j = 0; j < 64; ++j) {
            const float4* e4 = reinterpret_cast<const float4*>(&tile[j * ST]);
            float d0 = 0.f, d1 = 0.f, d2 = 0.f, d3 = 0.f;
            #pragma unroll
            for (int q = 0; q < 16; ++q) {
                float4 e = e4[q];
                d0 = __fmaf_rn(zr[q].x, e.x, d0);
                d1 = __fmaf_rn(zr[q].y, e.y, d1);
                d2 = __fmaf_rn(zr[q].z, e.z, d2);
                d3 = __fmaf_rn(zr[q].w, e.w, d3);
            }
            float dot = __fadd_rn(__fadd_rn(d0, d1), __fadd_rn(d2, d3));
            // d = (zn + en_j) - 2*dot, with the reference's double rounding
            float dval = __fadd_rn(__fadd_rn(zn, sn[j]), -__fmul_rn(2.0f, dot));
            if (dval < best) { best = dval; bestIdx = tile0 + j; }
        }
    }

    g_idx[n] = bestIdx;
    out[O_IDX + n] = (float)bestIdx;
    row[bestIdx] = 1.0f;                  // after this thread's own zero-stores

    // scatter cluster stats from the register-resident z row
    atomicAdd(&g_cs[bestIdx], 1.0f);
    float* s = g_sum + bestIdx * E_DIM;
    #pragma unroll
    for (int q = 0; q < 16; ++q) {
        atomicAdd(&s[4*q+0], zr[q].x);
        atomicAdd(&s[4*q+1], zr[q].y);
        atomicAdd(&s[4*q+2], zr[q].z);
        atomicAdd(&s[4*q+3], zr[q].w);
    }
}

// ---------------------------------------------------------------------------
// Kernel 2: EMA cluster-size stats + normalizer + perplexity (1 small block)
// ---------------------------------------------------------------------------
__global__ void k_stats(const float* __restrict__ ema_cs,
                        float* __restrict__ out) {
    __shared__ float red[1024];
    const int j = threadIdx.x;
    const float KD = (float)(1.0 - 0.99);

    float cs  = g_cs[j];
    float ncs = __fadd_rn(__fmul_rn(DECAY, ema_cs[j]), __fmul_rn(KD, cs));

    red[j] = ncs;
    __syncthreads();
    for (int s = 512; s > 0; s >>= 1) {
        if (j < s) red[j] = __fadd_rn(red[j], red[j + s]);
        __syncthreads();
    }
    float nsum = red[0];
    __syncthreads();

    g_csn[j] = __fmul_rn(__fdiv_rn(__fadd_rn(ncs, EPSF),
                                   __fadd_rn(nsum, (float)N_E * EPSF)), nsum);

    // perplexity from raw cluster_size
    float avg = cs * (1.0f / (float)N_TOK);
    float pt  = __fmul_rn(avg, logf(__fadd_rn(avg, 1e-10f)));
    red[j] = pt;
    __syncthreads();
    for (int s = 512; s > 0; s >>= 1) {
        if (j < s) red[j] = __fadd_rn(red[j], red[j + s]);
        __syncthreads();
    }
    if (j == 0) out[O_PERP] = expf(-red[0]);
}

// ---------------------------------------------------------------------------
// Kernel 3: parallel codebook EMA update (was the 136us single-block bottleneck)
// ---------------------------------------------------------------------------
__global__ void k_emb(const float* __restrict__ ema_w) {
    const float KD = (float)(1.0 - 0.99);
    int i = blockIdx.x * 256 + threadIdx.x;   // 0..65535
    if (i < N_E * E_DIM) {
        int j = i >> 6;
        float nw = __fadd_rn(__fmul_rn(DECAY, ema_w[i]),
                             __fmul_rn(KD, g_sum[i]));
        g_emb[i] = __fdiv_rn(nw, g_csn[j]);
    }
}

// ---------------------------------------------------------------------------
// Kernel 4: z_q gather, straight-through output, loss accumulation
// ---------------------------------------------------------------------------
__global__ void k_zq(const float* __restrict__ z, float* __restrict__ out) {
    __shared__ float warpsum[8];
    int i = blockIdx.x * 256 + threadIdx.x;
    float acc = 0.f;
    if (i < N_ELEM) {
        int hw = i & 1023;
        int c  = (i >> 10) & 63;
        int b  = i >> 16;
        int n  = (b << 10) | hw;
        float q  = g_emb[g_idx[n] * E_DIM + c];
        float zv = z[i];
        float dq = __fsub_rn(q, zv);             // stop_grad(z_q) - z
        out[O_ZQ + i] = __fadd_rn(zv, dq);       // z + (z_q - z), ref rounding
        acc = __fmul_rn(dq, dq);
    }
    #pragma unroll
    for (int s = 16; s > 0; s >>= 1)
        acc += __shfl_down_sync(0xffffffffu, acc, s);
    int lane = threadIdx.x & 31, wid = threadIdx.x >> 5;
    if (lane == 0) warpsum[wid] = acc;
    __syncthreads();
    if (wid == 0) {
        float v = (lane < 8) ? warpsum[lane] : 0.f;
        #pragma unroll
        for (int s = 4; s > 0; s >>= 1)
            v += __shfl_down_sync(0xffffffffu, v, s);
        if (lane == 0) atomicAdd(&g_loss_acc, v);
    }
}

// ---------------------------------------------------------------------------
// Kernel 5: finalize loss
// ---------------------------------------------------------------------------
__global__ void k_loss(float* __restrict__ out) {
    out[O_LOSS] = __fmul_rn(BETA, __fdiv_rn(g_loss_acc, (float)N_ELEM));
}

// ---------------------------------------------------------------------------
extern "C" void kernel_launch(void* const* d_in, const int* in_sizes, int n_in,
                              void* d_out, int out_size) {
    const float* z      = (const float*)d_in[0];
    const float* emb_w  = (const float*)d_in[1];
    const float* ema_cs = (const float*)d_in[2];
    const float* ema_w  = (const float*)d_in[3];
    float* out = (float*)d_out;

    k_prep<<<(N_E + 255) / 256, 256>>>(emb_w);
    k_argmin<<<N_TOK / 128, 128>>>(z, emb_w, out);
    k_stats<<<1, 1024>>>(ema_cs, out);
    k_emb<<<(N_E * E_DIM + 255) / 256, 256>>>(ema_w);
    k_zq<<<(N_ELEM + 255) / 256, 256>>>(z, out);
    k_loss<<<1, 1>>>(out);
}

// round 4
// speedup vs baseline: 1.4680x; 1.1508x over previous
#include <cuda_runtime.h>
#include <cuda_bf16.h>
#include <math.h>

// Problem constants
#define N_TOK   32768      // 32 * 32 * 32
#define N_E     1024
#define E_DIM   64
#define N_ELEM  2097152    // 32*64*32*32
#define HW      1024
#define BETA    0.25f
#define DECAY   0.99f
#define EPSF    1e-5f

// Output layout (flattened reference tuple, float32)
#define O_LOSS   0
#define O_ZQ     1
#define O_PERP   (1 + N_ELEM)                       // 2097153
#define O_MINENC (2 + N_ELEM)                       // 2097154
#define O_IDX    (2 + N_ELEM + (size_t)N_TOK*N_E)   // 35651586

// Scratch (no allocations allowed -> device globals)
__device__ int   g_idx[N_TOK];
__device__ float g_enorm[N_E];
__device__ float g_cs[N_E];
__device__ float g_csn[N_E];
__device__ float g_sum[N_E * E_DIM];
__device__ float g_emb[N_E * E_DIM];
__device__ float g_loss_acc;

// ---------------------------------------------------------------------------
// Kernel 0: codebook norms + zero scratch
// ---------------------------------------------------------------------------
__global__ void k_prep(const float* __restrict__ emb) {
    int j = blockIdx.x * 256 + threadIdx.x;
    if (j < N_E) {
        const float* e = emb + j * E_DIM;
        float s0 = 0.f, s1 = 0.f, s2 = 0.f, s3 = 0.f;
        #pragma unroll
        for (int c = 0; c < E_DIM; c += 4) {
            s0 = __fmaf_rn(e[c+0], e[c+0], s0);
            s1 = __fmaf_rn(e[c+1], e[c+1], s1);
            s2 = __fmaf_rn(e[c+2], e[c+2], s2);
            s3 = __fmaf_rn(e[c+3], e[c+3], s3);
        }
        g_enorm[j] = __fadd_rn(__fadd_rn(s0, s1), __fadd_rn(s2, s3));
        g_cs[j] = 0.f;
        float4 z4 = make_float4(0.f, 0.f, 0.f, 0.f);
        float4* s = reinterpret_cast<float4*>(g_sum + j * E_DIM);
        #pragma unroll
        for (int c = 0; c < E_DIM / 4; ++c) s[c] = z4;
        if (j == 0) g_loss_acc = 0.f;
    }
}

// ---------------------------------------------------------------------------
// Kernel 1: per-token argmin over 1024 codes (fp32 GEMM + running min).
// Pure FFMA stream (one-hot moved to its own coalesced kernel).
// Fused at the end: idx writes + scatter-add stats from register z row.
// ---------------------------------------------------------------------------
#define ST 68   // padded row stride (floats), 16B aligned

__global__ __launch_bounds__(128, 2)
void k_argmin(const float* __restrict__ z,
              const float* __restrict__ emb,
              float* __restrict__ out) {
    __shared__ float tile[64 * ST];
    __shared__ float sn[64];

    const int t   = threadIdx.x;          // 0..127
    const int n0  = blockIdx.x * 128;     // first token of block (same batch b)
    const int b   = n0 >> 10;
    const int hw0 = n0 & 1023;
    const float* zb = z + (size_t)b * E_DIM * HW;

    // ---- stage z for this block's 128 tokens (2 groups of 64), copy own row to regs
    float4 zr[16];
    const int myGroup = t >> 6;
    #pragma unroll
    for (int g = 0; g < 2; ++g) {
        __syncthreads();
        #pragma unroll
        for (int k = 0; k < 32; ++k) {
            int c = k * 2 + (t >> 6);
            int i = t & 63;
            tile[i * ST + c] = zb[c * HW + hw0 + g * 64 + i];
        }
        __syncthreads();
        if (myGroup == g) {
            int local = t & 63;
            #pragma unroll
            for (int q = 0; q < 16; ++q)
                zr[q] = *reinterpret_cast<const float4*>(&tile[local * ST + 4 * q]);
        }
    }

    // ||z||^2 (common-mode per token; ordering-safe)
    float a0 = 0.f, a1 = 0.f, a2 = 0.f, a3 = 0.f;
    #pragma unroll
    for (int q = 0; q < 16; ++q) {
        a0 = __fmaf_rn(zr[q].x, zr[q].x, a0);
        a1 = __fmaf_rn(zr[q].y, zr[q].y, a1);
        a2 = __fmaf_rn(zr[q].z, zr[q].z, a2);
        a3 = __fmaf_rn(zr[q].w, zr[q].w, a3);
    }
    const float zn = __fadd_rn(__fadd_rn(a0, a1), __fadd_rn(a2, a3));

    float best = 3.4e38f;
    int bestIdx = 0;

    for (int tile0 = 0; tile0 < N_E; tile0 += 64) {
        __syncthreads();
        #pragma unroll
        for (int k = 0; k < 32; ++k) {
            int j = k * 2 + (t >> 6);
            int c = t & 63;
            tile[j * ST + c] = emb[(tile0 + j) * E_DIM + c];
        }
        if (t < 64) sn[t] = g_enorm[tile0 + t];
        __syncthreads();

        #pragma unroll 8
        for (int j = 0; j < 64; ++j) {
            const float4* e4 = reinterpret_cast<const float4*>(&tile[j * ST]);
            float d0 = 0.f, d1 = 0.f, d2 = 0.f, d3 = 0.f;
            #pragma unroll
            for (int q = 0; q < 16; ++q) {
                float4 e = e4[q];
                d0 = __fmaf_rn(zr[q].x, e.x, d0);
                d1 = __fmaf_rn(zr[q].y, e.y, d1);
                d2 = __fmaf_rn(zr[q].z, e.z, d2);
                d3 = __fmaf_rn(zr[q].w, e.w, d3);
            }
            float dot = __fadd_rn(__fadd_rn(d0, d1), __fadd_rn(d2, d3));
            // d = (zn + en_j) - 2*dot, with the reference's double rounding
            float dval = __fadd_rn(__fadd_rn(zn, sn[j]), -__fmul_rn(2.0f, dot));
            if (dval < best) { best = dval; bestIdx = tile0 + j; }
        }
    }

    const int n = n0 + t;
    g_idx[n] = bestIdx;
    out[O_IDX + n] = (float)bestIdx;

    // scatter cluster stats from the register-resident z row
    atomicAdd(&g_cs[bestIdx], 1.0f);
    float* s = g_sum + bestIdx * E_DIM;
    #pragma unroll
    for (int q = 0; q < 16; ++q) {
        atomicAdd(&s[4*q+0], zr[q].x);
        atomicAdd(&s[4*q+1], zr[q].y);
        atomicAdd(&s[4*q+2], zr[q].z);
        atomicAdd(&s[4*q+3], zr[q].w);
    }
}

// ---------------------------------------------------------------------------
// Kernel 2: fully-coalesced one-hot materialization.
// Region is 8B-aligned -> float2 stores; each warp writes 256B contiguous,
// full 32B sectors (no read-modify-write amplification).
// ---------------------------------------------------------------------------
__global__ __launch_bounds__(256)
void k_onehot(float* __restrict__ out) {
    int i = blockIdx.x * 256 + threadIdx.x;       // float2 index, 0..16777215
    int n = i >> 9;                               // 512 float2 per row
    int c = (i & 511) << 1;                       // first col of this float2
    int idx = g_idx[n];                           // broadcast within warp (L1 hit)
    float2 v;
    v.x = (c     == idx) ? 1.0f : 0.0f;
    v.y = (c + 1 == idx) ? 1.0f : 0.0f;
    reinterpret_cast<float2*>(out + O_MINENC)[i] = v;
}

// ---------------------------------------------------------------------------
// Kernel 3: EMA cluster-size stats + normalizer + perplexity (1 small block)
// ---------------------------------------------------------------------------
__global__ void k_stats(const float* __restrict__ ema_cs,
                        float* __restrict__ out) {
    __shared__ float red[1024];
    const int j = threadIdx.x;
    const float KD = (float)(1.0 - 0.99);

    float cs  = g_cs[j];
    float ncs = __fadd_rn(__fmul_rn(DECAY, ema_cs[j]), __fmul_rn(KD, cs));

    red[j] = ncs;
    __syncthreads();
    for (int s = 512; s > 0; s >>= 1) {
        if (j < s) red[j] = __fadd_rn(red[j], red[j + s]);
        __syncthreads();
    }
    float nsum = red[0];
    __syncthreads();

    g_csn[j] = __fmul_rn(__fdiv_rn(__fadd_rn(ncs, EPSF),
                                   __fadd_rn(nsum, (float)N_E * EPSF)), nsum);

    // perplexity from raw cluster_size
    float avg = cs * (1.0f / (float)N_TOK);
    float pt  = __fmul_rn(avg, logf(__fadd_rn(avg, 1e-10f)));
    red[j] = pt;
    __syncthreads();
    for (int s = 512; s > 0; s >>= 1) {
        if (j < s) red[j] = __fadd_rn(red[j], red[j + s]);
        __syncthreads();
    }
    if (j == 0) out[O_PERP] = expf(-red[0]);
}

// ---------------------------------------------------------------------------
// Kernel 4: parallel codebook EMA update
// ---------------------------------------------------------------------------
__global__ void k_emb(const float* __restrict__ ema_w) {
    const float KD = (float)(1.0 - 0.99);
    int i = blockIdx.x * 256 + threadIdx.x;   // 0..65535
    if (i < N_E * E_DIM) {
        int j = i >> 6;
        float nw = __fadd_rn(__fmul_rn(DECAY, ema_w[i]),
                             __fmul_rn(KD, g_sum[i]));
        g_emb[i] = __fdiv_rn(nw, g_csn[j]);
    }
}

// ---------------------------------------------------------------------------
// Kernel 5: z_q gather, straight-through output, loss accumulation
// ---------------------------------------------------------------------------
__global__ void k_zq(const float* __restrict__ z, float* __restrict__ out) {
    __shared__ float warpsum[8];
    int i = blockIdx.x * 256 + threadIdx.x;
    float acc = 0.f;
    if (i < N_ELEM) {
        int hw = i & 1023;
        int c  = (i >> 10) & 63;
        int b  = i >> 16;
        int n  = (b << 10) | hw;
        float q  = g_emb[g_idx[n] * E_DIM + c];
        float zv = z[i];
        float dq = __fsub_rn(q, zv);             // stop_grad(z_q) - z
        out[O_ZQ + i] = __fadd_rn(zv, dq);       // z + (z_q - z), ref rounding
        acc = __fmul_rn(dq, dq);
    }
    #pragma unroll
    for (int s = 16; s > 0; s >>= 1)
        acc += __shfl_down_sync(0xffffffffu, acc, s);
    int lane = threadIdx.x & 31, wid = threadIdx.x >> 5;
    if (lane == 0) warpsum[wid] = acc;
    __syncthreads();
    if (wid == 0) {
        float v = (lane < 8) ? warpsum[lane] : 0.f;
        #pragma unroll
        for (int s = 4; s > 0; s >>= 1)
            v += __shfl_down_sync(0xffffffffu, v, s);
        if (lane == 0) atomicAdd(&g_loss_acc, v);
    }
}

// ---------------------------------------------------------------------------
// Kernel 6: finalize loss
// ---------------------------------------------------------------------------
__global__ void k_loss(float* __restrict__ out) {
    out[O_LOSS] = __fmul_rn(BETA, __fdiv_rn(g_loss_acc, (float)N_ELEM));
}

// ---------------------------------------------------------------------------
extern "C" void kernel_launch(void* const* d_in, const int* in_sizes, int n_in,
                              void* d_out, int out_size) {
    const float* z      = (const float*)d_in[0];
    const float* emb_w  = (const float*)d_in[1];
    const float* ema_cs = (const float*)d_in[2];
    const float* ema_w  = (const float*)d_in[3];
    float* out = (float*)d_out;

    k_prep<<<(N_E + 255) / 256, 256>>>(emb_w);
    k_argmin<<<N_TOK / 128, 128>>>(z, emb_w, out);
    k_onehot<<<(N_TOK * (N_E / 2)) / 256, 256>>>(out);
    k_stats<<<1, 1024>>>(ema_cs, out);
    k_emb<<<(N_E * E_DIM + 255) / 256, 256>>>(ema_w);
    k_zq<<<(N_ELEM + 255) / 256, 256>>>(z, out);
    k_loss<<<1, 1>>>(out);
}

// round 5
// speedup vs baseline: 1.5859x; 1.0803x over previous
#include <cuda_runtime.h>
#include <cuda_bf16.h>
#include <math.h>

// Problem constants
#define N_TOK   32768      // 32 * 32 * 32
#define N_E     1024
#define E_DIM   64
#define N_ELEM  2097152    // 32*64*32*32
#define HW      1024
#define BETA    0.25f
#define DECAY   0.99f
#define EPSF    1e-5f

// Output layout (flattened reference tuple, float32)
#define O_LOSS   0
#define O_ZQ     1
#define O_PERP   (1 + N_ELEM)                       // 2097153
#define O_MINENC (2 + N_ELEM)                       // 2097154
#define O_IDX    (2 + N_ELEM + (size_t)N_TOK*N_E)   // 35651586

// Scratch (no allocations allowed -> device globals)
__device__ int   g_idx[N_TOK];
__device__ float g_enorm[N_E];
__device__ float g_cs[N_E];
__device__ float g_csn[N_E];
__device__ float g_sum[N_E * E_DIM];
__device__ float g_emb[N_E * E_DIM];
__device__ float g_loss_acc;

// ---- packed f32x2 helpers (Blackwell FFMA2: one issue slot, two fp32 MACs,
//      IEEE-identical per lane to scalar FFMA) ----
#define FMA2(d, a, b, c) \
    asm("fma.rn.f32x2 %0, %1, %2, %3;" : "=l"(d) : "l"(a), "l"(b), "l"(c))
#define UNPACK2(lo, hi, v) \
    asm("mov.b64 {%0, %1}, %2;" : "=f"(lo), "=f"(hi) : "l"(v))
#define PACK2(v, lo, hi) \
    asm("mov.b64 %0, {%1, %2};" : "=l"(v) : "f"(lo), "f"(hi))
// shared-memory 16B load with literal offset (no per-load IADD in SASS)
#define LDSV2(e01, e23, base, OFF) \
    asm("ld.shared.v2.u64 {%0, %1}, [%2+" #OFF "];" \
        : "=l"(e01), "=l"(e23) : "r"(base))

// ---------------------------------------------------------------------------
// Kernel 0: codebook norms + zero scratch
// ---------------------------------------------------------------------------
__global__ void k_prep(const float* __restrict__ emb) {
    int j = blockIdx.x * 256 + threadIdx.x;
    if (j < N_E) {
        const float* e = emb + j * E_DIM;
        float s0 = 0.f, s1 = 0.f, s2 = 0.f, s3 = 0.f;
        #pragma unroll
        for (int c = 0; c < E_DIM; c += 4) {
            s0 = __fmaf_rn(e[c+0], e[c+0], s0);
            s1 = __fmaf_rn(e[c+1], e[c+1], s1);
            s2 = __fmaf_rn(e[c+2], e[c+2], s2);
            s3 = __fmaf_rn(e[c+3], e[c+3], s3);
        }
        g_enorm[j] = __fadd_rn(__fadd_rn(s0, s1), __fadd_rn(s2, s3));
        g_cs[j] = 0.f;
        float4 z4 = make_float4(0.f, 0.f, 0.f, 0.f);
        float4* s = reinterpret_cast<float4*>(g_sum + j * E_DIM);
        #pragma unroll
        for (int c = 0; c < E_DIM / 4; ++c) s[c] = z4;
        if (j == 0) g_loss_acc = 0.f;
    }
}

// ---------------------------------------------------------------------------
// Kernel 1: per-token argmin over 1024 codes.
// Inner product via packed fma.rn.f32x2 (FFMA2): 32 dual-MAC instructions per
// code instead of 64 scalar FFMA -> ~2x issue throughput, bitwise-identical
// accumulation per lane (lanes carry the old d0/d1 and d2/d3 chains).
// ---------------------------------------------------------------------------
#define ST 68   // padded row stride (floats); row stride 272B (16B-aligned)

__global__ __launch_bounds__(128, 2)
void k_argmin(const float* __restrict__ z,
              const float* __restrict__ emb,
              float* __restrict__ out) {
    __shared__ __align__(16) float tile[64 * ST];
    __shared__ float sn[64];

    const int t   = threadIdx.x;          // 0..127
    const int n0  = blockIdx.x * 128;     // first token of block (same batch b)
    const int b   = n0 >> 10;
    const int hw0 = n0 & 1023;
    const float* zb = z + (size_t)b * E_DIM * HW;

    // ---- stage z for this block's 128 tokens (2 groups of 64); own row -> regs
    float4 zr[16];
    const int myGroup = t >> 6;
    #pragma unroll
    for (int g = 0; g < 2; ++g) {
        __syncthreads();
        #pragma unroll
        for (int k = 0; k < 32; ++k) {
            int c = k * 2 + (t >> 6);
            int i = t & 63;
            tile[i * ST + c] = zb[c * HW + hw0 + g * 64 + i];
        }
        __syncthreads();
        if (myGroup == g) {
            int local = t & 63;
            #pragma unroll
            for (int q = 0; q < 16; ++q)
                zr[q] = *reinterpret_cast<const float4*>(&tile[local * ST + 4 * q]);
        }
    }

    // pack z row into 32 b64 pairs: zp[2q]=(x,y), zp[2q+1]=(z,w) of zr[q]
    unsigned long long zp[32];
    #pragma unroll
    for (int q = 0; q < 16; ++q) {
        PACK2(zp[2*q+0], zr[q].x, zr[q].y);
        PACK2(zp[2*q+1], zr[q].z, zr[q].w);
    }

    // ||z||^2 with the same per-lane accumulation order as before
    {
        unsigned long long na = 0ull, nb = 0ull;   // (0.f,0.f) packed
        #pragma unroll
        for (int q = 0; q < 16; ++q) {
            FMA2(na, zp[2*q+0], zp[2*q+0], na);
            FMA2(nb, zp[2*q+1], zp[2*q+1], nb);
        }
        float a0, a1, a2, a3;
        UNPACK2(a0, a1, na);
        UNPACK2(a2, a3, nb);
        zr[0].x = __fadd_rn(__fadd_rn(a0, a1), __fadd_rn(a2, a3)); // zn stash
    }
    const float zn = zr[0].x;

    float best = 3.4e38f;
    int bestIdx = 0;

    const unsigned tbase = (unsigned)__cvta_generic_to_shared(tile);

    for (int tile0 = 0; tile0 < N_E; tile0 += 64) {
        __syncthreads();
        #pragma unroll
        for (int k = 0; k < 32; ++k) {
            int j = k * 2 + (t >> 6);
            int c = t & 63;
            tile[j * ST + c] = emb[(tile0 + j) * E_DIM + c];
        }
        if (t < 64) sn[t] = g_enorm[tile0 + t];
        __syncthreads();

        #pragma unroll 4
        for (int j = 0; j < 64; ++j) {
            const unsigned rowa = tbase + (unsigned)(j * (ST * 4));
            unsigned long long acc_a = 0ull, acc_b = 0ull;
            unsigned long long e01, e23;
            // 16 x (LDS.128 broadcast + 2 FFMA2), literal offsets
            LDSV2(e01, e23, rowa,   0); FMA2(acc_a, zp[ 0], e01, acc_a); FMA2(acc_b, zp[ 1], e23, acc_b);
            LDSV2(e01, e23, rowa,  16); FMA2(acc_a, zp[ 2], e01, acc_a); FMA2(acc_b, zp[ 3], e23, acc_b);
            LDSV2(e01, e23, rowa,  32); FMA2(acc_a, zp[ 4], e01, acc_a); FMA2(acc_b, zp[ 5], e23, acc_b);
            LDSV2(e01, e23, rowa,  48); FMA2(acc_a, zp[ 6], e01, acc_a); FMA2(acc_b, zp[ 7], e23, acc_b);
            LDSV2(e01, e23, rowa,  64); FMA2(acc_a, zp[ 8], e01, acc_a); FMA2(acc_b, zp[ 9], e23, acc_b);
            LDSV2(e01, e23, rowa,  80); FMA2(acc_a, zp[10], e01, acc_a); FMA2(acc_b, zp[11], e23, acc_b);
            LDSV2(e01, e23, rowa,  96); FMA2(acc_a, zp[12], e01, acc_a); FMA2(acc_b, zp[13], e23, acc_b);
            LDSV2(e01, e23, rowa, 112); FMA2(acc_a, zp[14], e01, acc_a); FMA2(acc_b, zp[15], e23, acc_b);
            LDSV2(e01, e23, rowa, 128); FMA2(acc_a, zp[16], e01, acc_a); FMA2(acc_b, zp[17], e23, acc_b);
            LDSV2(e01, e23, rowa, 144); FMA2(acc_a, zp[18], e01, acc_a); FMA2(acc_b, zp[19], e23, acc_b);
            LDSV2(e01, e23, rowa, 160); FMA2(acc_a, zp[20], e01, acc_a); FMA2(acc_b, zp[21], e23, acc_b);
            LDSV2(e01, e23, rowa, 176); FMA2(acc_a, zp[22], e01, acc_a); FMA2(acc_b, zp[23], e23, acc_b);
            LDSV2(e01, e23, rowa, 192); FMA2(acc_a, zp[24], e01, acc_a); FMA2(acc_b, zp[25], e23, acc_b);
            LDSV2(e01, e23, rowa, 208); FMA2(acc_a, zp[26], e01, acc_a); FMA2(acc_b, zp[27], e23, acc_b);
            LDSV2(e01, e23, rowa, 224); FMA2(acc_a, zp[28], e01, acc_a); FMA2(acc_b, zp[29], e23, acc_b);
            LDSV2(e01, e23, rowa, 240); FMA2(acc_a, zp[30], e01, acc_a); FMA2(acc_b, zp[31], e23, acc_b);

            float d0, d1, d2, d3;
            UNPACK2(d0, d1, acc_a);
            UNPACK2(d2, d3, acc_b);
            float dot = __fadd_rn(__fadd_rn(d0, d1), __fadd_rn(d2, d3));
            // d = (zn + en_j) - 2*dot, with the reference's double rounding
            float dval = __fadd_rn(__fadd_rn(zn, sn[j]), -__fmul_rn(2.0f, dot));
            if (dval < best) { best = dval; bestIdx = tile0 + j; }
        }
    }

    const int n = n0 + t;
    g_idx[n] = bestIdx;
    out[O_IDX + n] = (float)bestIdx;

    // scatter cluster stats from the register-resident z row
    atomicAdd(&g_cs[bestIdx], 1.0f);
    float* s = g_sum + bestIdx * E_DIM;
    #pragma unroll
    for (int q = 0; q < 32; ++q) {
        float lo, hi;
        UNPACK2(lo, hi, zp[q]);
        atomicAdd(&s[2*q+0], lo);
        atomicAdd(&s[2*q+1], hi);
    }
}

// ---------------------------------------------------------------------------
// Kernel 2: fully-coalesced one-hot materialization (float2, full sectors)
// ---------------------------------------------------------------------------
__global__ __launch_bounds__(256)
void k_onehot(float* __restrict__ out) {
    int i = blockIdx.x * 256 + threadIdx.x;       // float2 index, 0..16777215
    int n = i >> 9;                               // 512 float2 per row
    int c = (i & 511) << 1;                       // first col of this float2
    int idx = g_idx[n];                           // broadcast within warp
    float2 v;
    v.x = (c     == idx) ? 1.0f : 0.0f;
    v.y = (c + 1 == idx) ? 1.0f : 0.0f;
    reinterpret_cast<float2*>(out + O_MINENC)[i] = v;
}

// ---------------------------------------------------------------------------
// Kernel 3: EMA cluster-size stats + normalizer + perplexity (1 small block)
// ---------------------------------------------------------------------------
__global__ void k_stats(const float* __restrict__ ema_cs,
                        float* __restrict__ out) {
    __shared__ float red[1024];
    const int j = threadIdx.x;
    const float KD = (float)(1.0 - 0.99);

    float cs  = g_cs[j];
    float ncs = __fadd_rn(__fmul_rn(DECAY, ema_cs[j]), __fmul_rn(KD, cs));

    red[j] = ncs;
    __syncthreads();
    for (int s = 512; s > 0; s >>= 1) {
        if (j < s) red[j] = __fadd_rn(red[j], red[j + s]);
        __syncthreads();
    }
    float nsum = red[0];
    __syncthreads();

    g_csn[j] = __fmul_rn(__fdiv_rn(__fadd_rn(ncs, EPSF),
                                   __fadd_rn(nsum, (float)N_E * EPSF)), nsum);

    float avg = cs * (1.0f / (float)N_TOK);
    float pt  = __fmul_rn(avg, logf(__fadd_rn(avg, 1e-10f)));
    red[j] = pt;
    __syncthreads();
    for (int s = 512; s > 0; s >>= 1) {
        if (j < s) red[j] = __fadd_rn(red[j], red[j + s]);
        __syncthreads();
    }
    if (j == 0) out[O_PERP] = expf(-red[0]);
}

// ---------------------------------------------------------------------------
// Kernel 4: parallel codebook EMA update
// ---------------------------------------------------------------------------
__global__ void k_emb(const float* __restrict__ ema_w) {
    const float KD = (float)(1.0 - 0.99);
    int i = blockIdx.x * 256 + threadIdx.x;   // 0..65535
    if (i < N_E * E_DIM) {
        int j = i >> 6;
        float nw = __fadd_rn(__fmul_rn(DECAY, ema_w[i]),
                             __fmul_rn(KD, g_sum[i]));
        g_emb[i] = __fdiv_rn(nw, g_csn[j]);
    }
}

// ---------------------------------------------------------------------------
// Kernel 5: z_q gather, straight-through output, loss accumulation
// ---------------------------------------------------------------------------
__global__ void k_zq(const float* __restrict__ z, float* __restrict__ out) {
    __shared__ float warpsum[8];
    int i = blockIdx.x * 256 + threadIdx.x;
    float acc = 0.f;
    if (i < N_ELEM) {
        int hw = i & 1023;
        int c  = (i >> 10) & 63;
        int b  = i >> 16;
        int n  = (b << 10) | hw;
        float q  = g_emb[g_idx[n] * E_DIM + c];
        float zv = z[i];
        float dq = __fsub_rn(q, zv);             // stop_grad(z_q) - z
        out[O_ZQ + i] = __fadd_rn(zv, dq);       // z + (z_q - z), ref rounding
        acc = __fmul_rn(dq, dq);
    }
    #pragma unroll
    for (int s = 16; s > 0; s >>= 1)
        acc += __shfl_down_sync(0xffffffffu, acc, s);
    int lane = threadIdx.x & 31, wid = threadIdx.x >> 5;
    if (lane == 0) warpsum[wid] = acc;
    __syncthreads();
    if (wid == 0) {
        float v = (lane < 8) ? warpsum[lane] : 0.f;
        #pragma unroll
        for (int s = 4; s > 0; s >>= 1)
            v += __shfl_down_sync(0xffffffffu, v, s);
        if (lane == 0) atomicAdd(&g_loss_acc, v);
    }
}

// ---------------------------------------------------------------------------
// Kernel 6: finalize loss
// ---------------------------------------------------------------------------
__global__ void k_loss(float* __restrict__ out) {
    out[O_LOSS] = __fmul_rn(BETA, __fdiv_rn(g_loss_acc, (float)N_ELEM));
}

// ---------------------------------------------------------------------------
extern "C" void kernel_launch(void* const* d_in, const int* in_sizes, int n_in,
                              void* d_out, int out_size) {
    const float* z      = (const float*)d_in[0];
    const float* emb_w  = (const float*)d_in[1];
    const float* ema_cs = (const float*)d_in[2];
    const float* ema_w  = (const float*)d_in[3];
    float* out = (float*)d_out;

    k_prep<<<(N_E + 255) / 256, 256>>>(emb_w);
    k_argmin<<<N_TOK / 128, 128>>>(z, emb_w, out);
    k_onehot<<<(N_TOK * (N_E / 2)) / 256, 256>>>(out);
    k_stats<<<1, 1024>>>(ema_cs, out);
    k_emb<<<(N_E * E_DIM + 255) / 256, 256>>>(ema_w);
    k_zq<<<(N_ELEM + 255) / 256, 256>>>(z, out);
    k_loss<<<1, 1>>>(out);
}